// round 2
// baseline (speedup 1.0000x reference)
#include <cuda_runtime.h>
#include <cstdint>

// FPS on GB300, round 2.
// - One cluster per batch; cluster size 16 preferred (128 CTAs / 128 SMs),
//   runtime probe with cluster-8 fallback.
// - Coords SMEM-resident SoA, min-dist register-resident (float4 regs).
// - Per step: LDS.128 coord loads, packed f32x2 distance update (bit-exact
//   vs reference mul-then-add order), FMNMX max tree + equality scan for the
//   thread-local argmax, REDUX warp/CTA reduces, DSMEM candidate exchange via
//   st.shared::cluster + mbarrier.arrive.release.cluster (no barrier.cluster
//   in the loop), parity-phased wait, double-buffered slots.

#define NPTS     131072
#define BATCH    8
#define NSAMP    4096
#define NTHREADS 1024
#define BIGF     1e10f

#define ADD2(o, a, b) asm("add.rn.f32x2 %0, %1, %2;" : "=l"(o) : "l"(a), "l"(b))
#define MUL2(o, a, b) asm("mul.rn.f32x2 %0, %1, %2;" : "=l"(o) : "l"(a), "l"(b))
#define PACK2(o, lo, hi) asm("mov.b64 %0, {%1, %2;}" : "=l"(o) : "f"(lo), "f"(hi))
// (note: correct form below; the macro above is unused)
#undef PACK2
#define PACK2(o, lo, hi) asm("mov.b64 %0, {%1, %2};" : "=l"(o) : "f"(lo), "f"(hi))
#define UNPACK2(lo, hi, in) asm("mov.b64 {%0, %1}, %2;" : "=f"(lo), "=f"(hi) : "l"(in))

static __device__ __forceinline__ uint32_t smem_u32(const void* p) {
    uint32_t a;
    asm("{ .reg .u64 t; cvta.to.shared.u64 t, %1; cvt.u32.u64 %0, t; }"
        : "=r"(a) : "l"(p));
    return a;
}
static __device__ __forceinline__ uint32_t mapa_rank(uint32_t local, uint32_t rank) {
    uint32_t r;
    asm("mapa.shared::cluster.u32 %0, %1, %2;" : "=r"(r) : "r"(local), "r"(rank));
    return r;
}
static __device__ __forceinline__ void st_cluster_b64(uint32_t addr, unsigned long long v) {
    asm volatile("st.shared::cluster.b64 [%0], %1;" :: "r"(addr), "l"(v) : "memory");
}
static __device__ __forceinline__ void st_cluster_b32(uint32_t addr, uint32_t v) {
    asm volatile("st.shared::cluster.b32 [%0], %1;" :: "r"(addr), "r"(v) : "memory");
}
static __device__ __forceinline__ void mbar_arrive_remote(uint32_t remote_mbar) {
    asm volatile("mbarrier.arrive.release.cluster.shared::cluster.b64 _, [%0];"
                 :: "r"(remote_mbar) : "memory");
}
static __device__ __forceinline__ void mbar_wait_cluster(uint32_t mbar, uint32_t parity) {
    asm volatile(
        "{\n\t"
        ".reg .pred P;\n\t"
        "WL_%=:\n\t"
        "mbarrier.try_wait.parity.acquire.cluster.shared::cta.b64 P, [%0], %1;\n\t"
        "@!P bra WL_%=;\n\t"
        "}" :: "r"(mbar), "r"(parity) : "memory");
}
static __device__ __forceinline__ unsigned long long f2_to_u64(float a, float b) {
    unsigned long long r;
    asm("mov.b64 %0, {%1, %2};" : "=l"(r) : "f"(a), "f"(b));
    return r;
}

template <int CS>
__device__ __forceinline__ void fps_body(const float* __restrict__ pts,
                                         float* __restrict__ out)
{
    constexpr int PPC    = NPTS / CS;             // points per CTA
    constexpr int QPT    = PPC / (4 * NTHREADS);  // float4-quads per thread
    constexpr int LOGPPC = (CS == 16) ? 13 : 14;

    extern __shared__ float sm[];
    float*    smx  = sm;
    float*    smy  = sm + PPC;
    float*    smz  = sm + 2 * PPC;
    unsigned* wv   = (unsigned*)(sm + 3 * PPC);   // [2][32] warp best value bits
    unsigned* wi   = wv + 64;                     // [2][32] warp best index
    float*    cand = (float*)(wi + 64);           // [2][CS][8] candidate slots
    unsigned long long* mbar = (unsigned long long*)(cand + 2 * CS * 8);

    const int tid  = threadIdx.x;
    const int lane = tid & 31;
    const int warp = tid >> 5;
    uint32_t rank;
    asm("mov.u32 %0, %%cluster_ctarank;" : "=r"(rank));
    const int b = blockIdx.x / CS;
    const float* P = pts + (size_t)b * NPTS * 3;
    const int base = (int)rank * PPC;

    // Load this CTA's coords into SMEM (SoA).
    for (int i = tid; i < PPC; i += NTHREADS) {
        const float* g = P + (size_t)(base + i) * 3;
        smx[i] = g[0];
        smy[i] = g[1];
        smz[i] = g[2];
    }
    const uint32_t mbar_u32 = smem_u32(mbar);
    const uint32_t cand_u32 = smem_u32(cand);
    if (tid == 0) {
        asm volatile("mbarrier.init.shared.b64 [%0], %1;"
                     :: "r"(mbar_u32), "r"((unsigned)CS) : "memory");
    }
    __syncthreads();
    // One cluster barrier at startup: publishes mbarrier init + smem coords.
    asm volatile("barrier.cluster.arrive.aligned;" ::: "memory");
    asm volatile("barrier.cluster.wait.aligned;" ::: "memory");

    float4 md[QPT];
#pragma unroll
    for (int j = 0; j < QPT; j++) md[j] = make_float4(BIGF, BIGF, BIGF, BIGF);

    float lx = P[0], ly = P[1], lz = P[2];   // reference: last_idx init = 0
    const int t4 = 4 * tid;

    // Hoisted remote addresses for the publishing lanes (warp0, lane < CS).
    const uint32_t tgt = (uint32_t)(lane < CS ? lane : 0);
    const uint32_t remote_mbar = mapa_rank(mbar_u32, tgt);
    const uint32_t remote_slot0 = mapa_rank(cand_u32 + rank * 32u, tgt);

    for (int s = 0; s < NSAMP; s++) {
        const int p = s & 1;

        // Reference scan emits last_idx BEFORE the update.
        if (rank == 0 && tid == 0) {
            float* o = out + ((size_t)b * NSAMP + s) * 3;
            o[0] = lx; o[1] = ly; o[2] = lz;
        }

        unsigned long long NX, NY, NZ;
        {
            float nx = -lx, ny = -ly, nz = -lz;  // x + (-l) == x - l bit-exact (rn)
            PACK2(NX, nx, nx);
            PACK2(NY, ny, ny);
            PACK2(NZ, nz, nz);
        }

        // Distance update, 4 points per quad via LDS.128 + f32x2.
#pragma unroll
        for (int j = 0; j < QPT; j++) {
            const int q4 = j * NTHREADS + tid;
            float4 X = ((const float4*)smx)[q4];
            float4 Y = ((const float4*)smy)[q4];
            float4 Z = ((const float4*)smz)[q4];
            unsigned long long xa, xb, ya, yb, za, zb, sa, sb;
            PACK2(xa, X.x, X.y); PACK2(xb, X.z, X.w);
            PACK2(ya, Y.x, Y.y); PACK2(yb, Y.z, Y.w);
            PACK2(za, Z.x, Z.y); PACK2(zb, Z.z, Z.w);
            ADD2(xa, xa, NX); MUL2(xa, xa, xa);
            ADD2(ya, ya, NY); MUL2(ya, ya, ya);
            ADD2(za, za, NZ); MUL2(za, za, za);
            ADD2(sa, xa, ya);            // (dx^2 + dy^2)
            ADD2(sa, sa, za);            // + dz^2 — same order as jnp.sum
            ADD2(xb, xb, NX); MUL2(xb, xb, xb);
            ADD2(yb, yb, NY); MUL2(yb, yb, yb);
            ADD2(zb, zb, NZ); MUL2(zb, zb, zb);
            ADD2(sb, xb, yb);
            ADD2(sb, sb, zb);
            float d0, d1, d2, d3;
            UNPACK2(d0, d1, sa);
            UNPACK2(d2, d3, sb);
            md[j].x = fminf(md[j].x, d0);
            md[j].y = fminf(md[j].y, d1);
            md[j].z = fminf(md[j].z, d2);
            md[j].w = fminf(md[j].w, d3);
        }

        // Thread-local max (FMNMX tree), then first-index-equal scan
        // (descending overwrite => lowest index wins => jnp.argmax tie rule).
        float bestv = md[0].x;
#pragma unroll
        for (int j = 0; j < QPT; j++) {
            bestv = fmaxf(bestv, md[j].x);
            bestv = fmaxf(bestv, md[j].y);
            bestv = fmaxf(bestv, md[j].z);
            bestv = fmaxf(bestv, md[j].w);
        }
        int besti = 0;
#pragma unroll
        for (int j = QPT - 1; j >= 0; j--) {
            const int ib = 4 * j * NTHREADS + t4;
            if (md[j].w == bestv) besti = ib + 3;
            if (md[j].z == bestv) besti = ib + 2;
            if (md[j].y == bestv) besti = ib + 1;
            if (md[j].x == bestv) besti = ib + 0;
        }

        // Warp reduce via REDUX: max value bits (nonneg fp32 => monotonic as
        // u32), then min index among max holders.
        unsigned vb   = __float_as_uint(bestv);
        unsigned wmax = __reduce_max_sync(0xffffffffu, vb);
        unsigned imin = __reduce_min_sync(0xffffffffu,
                                          vb == wmax ? (unsigned)besti : 0xffffffffu);
        if (lane == 0) { wv[p * 32 + warp] = wmax; wi[p * 32 + warp] = imin; }
        __syncthreads();

        // CTA reduce: every warp reduces the 32 warp-candidates identically.
        unsigned v2   = wv[p * 32 + lane];
        unsigned i2   = wi[p * 32 + lane];
        unsigned cmax = __reduce_max_sync(0xffffffffu, v2);
        unsigned csel = __reduce_min_sync(0xffffffffu,
                                          v2 == cmax ? i2 : 0xffffffffu);

        // Warp 0 lanes 0..CS-1 publish {vbits, gidx, x, y, z} to slot
        // [p][rank] of every cluster CTA, then arrive (release) on each
        // remote mbarrier.
        if (warp == 0 && lane < CS) {
            float cx = smx[csel], cy = smy[csel], cz = smz[csel];
            unsigned gi = (unsigned)(base + (int)csel);
            uint32_t dst = remote_slot0 + (uint32_t)(p * CS * 32);
            st_cluster_b64(dst,
                           (unsigned long long)cmax | ((unsigned long long)gi << 32));
            st_cluster_b64(dst + 8, f2_to_u64(cx, cy));
            st_cluster_b32(dst + 16, __float_as_uint(cz));
            mbar_arrive_remote(remote_mbar);
        }

        // Wait for all CS arrivals of this phase (acquire, cluster scope).
        mbar_wait_cluster(mbar_u32, (uint32_t)p);

        // Cluster reduce: lanes < CS hold one candidate each; REDUX picks the
        // winner; winning lane recovered as gsel >> log2(PPC); shfl coords.
        const float* slot = cand + (p * CS + lane) * 8;
        unsigned gv = 0, ggi = 0xffffffffu;
        float gx = 0.f, gy = 0.f, gz = 0.f;
        if (lane < CS) {
            gv  = ((const unsigned*)slot)[0];
            ggi = ((const unsigned*)slot)[1];
            gx  = slot[2];
            gy  = slot[3];
            gz  = slot[4];
        }
        unsigned gmax = __reduce_max_sync(0xffffffffu, gv);
        unsigned gsel = __reduce_min_sync(0xffffffffu,
                                          (lane < CS && gv == gmax) ? ggi : 0xffffffffu);
        const int wl = (int)(gsel >> LOGPPC);
        lx = __shfl_sync(0xffffffffu, gx, wl);
        ly = __shfl_sync(0xffffffffu, gy, wl);
        lz = __shfl_sync(0xffffffffu, gz, wl);
    }
}

__global__ void __cluster_dims__(16, 1, 1) __launch_bounds__(NTHREADS, 1)
fps16(const float* __restrict__ pts, float* __restrict__ out) { fps_body<16>(pts, out); }

__global__ void __cluster_dims__(8, 1, 1) __launch_bounds__(NTHREADS, 1)
fps8(const float* __restrict__ pts, float* __restrict__ out) { fps_body<8>(pts, out); }

static size_t smem_bytes(int cs) {
    int ppc = NPTS / cs;
    return (size_t)(3 * ppc + 64 + 64 + 2 * cs * 8 + 2) * sizeof(float);
}

extern "C" void kernel_launch(void* const* d_in, const int* in_sizes, int n_in,
                              void* d_out, int out_size)
{
    (void)in_sizes; (void)n_in; (void)out_size;
    const float* pts = (const float*)d_in[0];   // point_coord (8, 131072, 3)
    float* out = (float*)d_out;                 // (8, 4096, 3)

    const size_t s16 = smem_bytes(16);
    const size_t s8  = smem_bytes(8);

    cudaFuncSetAttribute(fps16, cudaFuncAttributeNonPortableClusterSizeAllowed, 1);
    cudaFuncSetAttribute(fps16, cudaFuncAttributeMaxDynamicSharedMemorySize, (int)s16);
    cudaFuncSetAttribute(fps8,  cudaFuncAttributeMaxDynamicSharedMemorySize, (int)s8);
    cudaGetLastError();  // clear any attr-set error

    // Probe: can the device actually run 16-CTA clusters of this shape?
    int nc = 0;
    cudaLaunchConfig_t cfg = {};
    cfg.gridDim  = dim3(BATCH * 16, 1, 1);
    cfg.blockDim = dim3(NTHREADS, 1, 1);
    cfg.dynamicSmemBytes = s16;
    cudaLaunchAttribute at[1];
    at[0].id = cudaLaunchAttributeClusterDimension;
    at[0].val.clusterDim.x = 16;
    at[0].val.clusterDim.y = 1;
    at[0].val.clusterDim.z = 1;
    cfg.attrs = at;
    cfg.numAttrs = 1;
    cudaError_t e = cudaOccupancyMaxActiveClusters(&nc, fps16, &cfg);

    if (e == cudaSuccess && nc > 0) {
        fps16<<<BATCH * 16, NTHREADS, s16>>>(pts, out);
    } else {
        cudaGetLastError();  // clear probe error
        fps8<<<BATCH * 8, NTHREADS, s8>>>(pts, out);
    }
}

// round 3
// speedup vs baseline: 1.3176x; 1.3176x over previous
#include <cuda_runtime.h>
#include <cstdint>

// FPS on GB300, round 3.
// CS=16 clusters (128 CTAs), 512 threads/CTA, coords register-resident
// (packed f32x2), min-dist register-resident. SMEM holds a coords copy only
// for winner-xyz lookup. Reduce: REDUX(max bits)+REDUX(min idx) per stage.
// Cluster exchange: DSMEM stores + barrier.cluster (proven R1 primitive),
// parity double-buffered candidate slots. Bit-exact vs reference:
// mul-then-add order, first-index tie-break everywhere.

#define NPTS     131072
#define BATCH    8
#define NSAMP    4096
#define NT       512
#define BIGF     1e10f

#define ADD2(o, a, b) asm("add.rn.f32x2 %0, %1, %2;" : "=l"(o) : "l"(a), "l"(b))
#define MUL2(o, a, b) asm("mul.rn.f32x2 %0, %1, %2;" : "=l"(o) : "l"(a), "l"(b))
#define PACK2(o, lo, hi) asm("mov.b64 %0, {%1, %2};" : "=l"(o) : "f"(lo), "f"(hi))
#define UNPACK2(lo, hi, in) asm("mov.b64 {%0, %1}, %2;" : "=f"(lo), "=f"(hi) : "l"(in))

static __device__ __forceinline__ uint32_t smem_u32(const void* p) {
    uint32_t a;
    asm("{ .reg .u64 t; cvta.to.shared.u64 t, %1; cvt.u32.u64 %0, t; }"
        : "=r"(a) : "l"(p));
    return a;
}
static __device__ __forceinline__ uint32_t mapa_rank(uint32_t local, uint32_t rank) {
    uint32_t r;
    asm("mapa.shared::cluster.u32 %0, %1, %2;" : "=r"(r) : "r"(local), "r"(rank));
    return r;
}
static __device__ __forceinline__ void st_cluster_b64(uint32_t addr, unsigned long long v) {
    asm volatile("st.shared::cluster.b64 [%0], %1;" :: "r"(addr), "l"(v) : "memory");
}
static __device__ __forceinline__ void st_cluster_b32(uint32_t addr, uint32_t v) {
    asm volatile("st.shared::cluster.b32 [%0], %1;" :: "r"(addr), "r"(v) : "memory");
}
static __device__ __forceinline__ unsigned long long f2_to_u64(float a, float b) {
    unsigned long long r;
    asm("mov.b64 %0, {%1, %2};" : "=l"(r) : "f"(a), "f"(b));
    return r;
}
static __device__ __forceinline__ void cluster_barrier() {
    asm volatile("barrier.cluster.arrive.aligned;" ::: "memory");
    asm volatile("barrier.cluster.wait.aligned;" ::: "memory");
}

// CS: cluster size. REGC: coords cached in registers (else read from SMEM).
template <int CS, bool REGC>
__device__ __forceinline__ void fps_body(const float* __restrict__ pts,
                                         float* __restrict__ out)
{
    constexpr int PPC    = NPTS / CS;          // points per CTA
    constexpr int QPT    = PPC / (4 * NT);     // 4-point quads per thread
    constexpr int LOGPPC = (CS == 16) ? 13 : 14;

    extern __shared__ float sm[];
    float*    smx  = sm;
    float*    smy  = sm + PPC;
    float*    smz  = sm + 2 * PPC;
    unsigned* wv   = (unsigned*)(sm + 3 * PPC);   // [32] per-warp best value bits
    unsigned* wi   = wv + 32;                     // [32] per-warp best local idx
    float*    cand = (float*)(wi + 32);           // [2][CS][8] candidate slots

    const int tid  = threadIdx.x;
    const int lane = tid & 31;
    const int warp = tid >> 5;
    uint32_t rank;
    asm("mov.u32 %0, %%cluster_ctarank;" : "=r"(rank));
    const int b = blockIdx.x / CS;
    const float* P = pts + (size_t)b * NPTS * 3;
    const int base = (int)rank * PPC;

    // Load this CTA's coords: SMEM SoA copy always (winner lookup), plus
    // packed f32x2 register cache when REGC.
    unsigned long long Xr[REGC ? 2 * QPT : 1];
    unsigned long long Yr[REGC ? 2 * QPT : 1];
    unsigned long long Zr[REGC ? 2 * QPT : 1];
#pragma unroll
    for (int j = 0; j < QPT; j++) {
        const int i0 = 4 * (j * NT + tid);        // first of 4 points
        float x[4], y[4], z[4];
#pragma unroll
        for (int k = 0; k < 4; k++) {
            const float* g = P + (size_t)(base + i0 + k) * 3;
            x[k] = g[0]; y[k] = g[1]; z[k] = g[2];
            smx[i0 + k] = x[k]; smy[i0 + k] = y[k]; smz[i0 + k] = z[k];
        }
        if (REGC) {
            PACK2(Xr[2 * j], x[0], x[1]); PACK2(Xr[2 * j + 1], x[2], x[3]);
            PACK2(Yr[2 * j], y[0], y[1]); PACK2(Yr[2 * j + 1], y[2], y[3]);
            PACK2(Zr[2 * j], z[0], z[1]); PACK2(Zr[2 * j + 1], z[2], z[3]);
        }
    }
    if (tid < 32) { wv[tid] = 0u; wi[tid] = 0xffffffffu; }  // pad warps 16..31

    float4 md[QPT];
#pragma unroll
    for (int j = 0; j < QPT; j++) md[j] = make_float4(BIGF, BIGF, BIGF, BIGF);

    __syncthreads();
    cluster_barrier();   // publish smem coords across cluster (and sync start)

    float lx = P[0], ly = P[1], lz = P[2];   // reference: last_idx init = 0
    const uint32_t cand_u32 = smem_u32(cand);
    const uint32_t tgt = (uint32_t)(lane < CS ? lane : 0);
    const uint32_t rslot0 = mapa_rank(cand_u32 + rank * 32u, tgt);
    const uint32_t rslot1 = rslot0 + (uint32_t)(CS * 32);

    for (int s = 0; s < NSAMP; s++) {
        const int p = s & 1;

        // Reference scan emits last_idx BEFORE the update.
        if (rank == 0 && tid == 0) {
            float* o = out + ((size_t)b * NSAMP + s) * 3;
            o[0] = lx; o[1] = ly; o[2] = lz;
        }

        unsigned long long NX, NY, NZ;
        {
            float nx = -lx, ny = -ly, nz = -lz;  // x + (-l) == x - l bit-exact (rn)
            PACK2(NX, nx, nx); PACK2(NY, ny, ny); PACK2(NZ, nz, nz);
        }

        // ---- distance update: 4 points per quad, packed f32x2 ----
#pragma unroll
        for (int j = 0; j < QPT; j++) {
            unsigned long long xa, xb, ya, yb, za, zb;
            if (REGC) {
                xa = Xr[2 * j]; xb = Xr[2 * j + 1];
                ya = Yr[2 * j]; yb = Yr[2 * j + 1];
                za = Zr[2 * j]; zb = Zr[2 * j + 1];
            } else {
                const int q4 = j * NT + tid;
                float4 X = ((const float4*)smx)[q4];
                float4 Y = ((const float4*)smy)[q4];
                float4 Z = ((const float4*)smz)[q4];
                PACK2(xa, X.x, X.y); PACK2(xb, X.z, X.w);
                PACK2(ya, Y.x, Y.y); PACK2(yb, Y.z, Y.w);
                PACK2(za, Z.x, Z.y); PACK2(zb, Z.z, Z.w);
            }
            unsigned long long sa, sb;
            ADD2(xa, xa, NX); MUL2(xa, xa, xa);
            ADD2(ya, ya, NY); MUL2(ya, ya, ya);
            ADD2(za, za, NZ); MUL2(za, za, za);
            ADD2(sa, xa, ya);          // (dx^2 + dy^2)
            ADD2(sa, sa, za);          // + dz^2 — same order as jnp.sum
            ADD2(xb, xb, NX); MUL2(xb, xb, xb);
            ADD2(yb, yb, NY); MUL2(yb, yb, yb);
            ADD2(zb, zb, NZ); MUL2(zb, zb, zb);
            ADD2(sb, xb, yb);
            ADD2(sb, sb, zb);
            float d0, d1, d2, d3;
            UNPACK2(d0, d1, sa);
            UNPACK2(d2, d3, sb);
            md[j].x = fminf(md[j].x, d0);
            md[j].y = fminf(md[j].y, d1);
            md[j].z = fminf(md[j].z, d2);
            md[j].w = fminf(md[j].w, d3);
        }

        // ---- thread-local argmax: FMNMX tree + reversed equality scan
        //      (descending overwrite => lowest index wins, jnp tie rule) ----
        float bestv = md[0].x;
#pragma unroll
        for (int j = 0; j < QPT; j++) {
            bestv = fmaxf(fmaxf(bestv, fmaxf(md[j].x, md[j].y)),
                          fmaxf(md[j].z, md[j].w));
        }
        int besti = 0;
#pragma unroll
        for (int j = QPT - 1; j >= 0; j--) {
            const int ib = 4 * (j * NT + tid);
            if (md[j].w == bestv) besti = ib + 3;
            if (md[j].z == bestv) besti = ib + 2;
            if (md[j].y == bestv) besti = ib + 1;
            if (md[j].x == bestv) besti = ib + 0;
        }

        // ---- warp reduce: REDUX max on value bits (nonneg fp32 monotonic
        //      as u32), REDUX min on idx among max holders ----
        unsigned vb   = __float_as_uint(bestv);
        unsigned wmax = __reduce_max_sync(0xffffffffu, vb);
        unsigned imin = __reduce_min_sync(0xffffffffu,
                                          vb == wmax ? (unsigned)besti : 0xffffffffu);
        if (lane == 0) { wv[warp] = wmax; wi[warp] = imin; }
        __syncthreads();

        // ---- CTA reduce (warp 0) + publish to all cluster CTAs ----
        if (warp == 0) {
            unsigned v2   = wv[lane];
            unsigned i2   = wi[lane];
            unsigned cmax = __reduce_max_sync(0xffffffffu, v2);
            unsigned csel = __reduce_min_sync(0xffffffffu,
                                              v2 == cmax ? i2 : 0xffffffffu);
            if (lane < CS) {
                float cx = smx[csel], cy = smy[csel], cz = smz[csel];
                unsigned gi = (unsigned)(base + (int)csel);
                uint32_t dst = p ? rslot1 : rslot0;
                st_cluster_b64(dst,
                               (unsigned long long)cmax | ((unsigned long long)gi << 32));
                st_cluster_b64(dst + 8, f2_to_u64(cx, cy));
                st_cluster_b32(dst + 16, __float_as_uint(cz));
            }
        }

        // One cluster barrier per step: releases the DSMEM stores, protects
        // the parity-buffered slots.
        cluster_barrier();

        // ---- cluster reduce: lanes < CS hold one candidate; REDUX picks
        //      winner; winning rank = gidx >> log2(PPC); shfl coords ----
        const float* slot = cand + (p * CS + lane) * 8;
        unsigned gv = 0u, ggi = 0xffffffffu;
        float gx = 0.f, gy = 0.f, gz = 0.f;
        if (lane < CS) {
            gv  = ((const unsigned*)slot)[0];
            ggi = ((const unsigned*)slot)[1];
            gx  = slot[2];
            gy  = slot[3];
            gz  = slot[4];
        }
        unsigned gmax = __reduce_max_sync(0xffffffffu, gv);
        unsigned gsel = __reduce_min_sync(0xffffffffu,
                                          (lane < CS && gv == gmax) ? ggi : 0xffffffffu);
        const int wl = (int)(gsel >> LOGPPC);
        lx = __shfl_sync(0xffffffffu, gx, wl);
        ly = __shfl_sync(0xffffffffu, gy, wl);
        lz = __shfl_sync(0xffffffffu, gz, wl);
    }
}

__global__ void __cluster_dims__(16, 1, 1) __launch_bounds__(NT, 1)
fps16(const float* __restrict__ pts, float* __restrict__ out) {
    fps_body<16, true>(pts, out);
}
__global__ void __cluster_dims__(8, 1, 1) __launch_bounds__(NT, 1)
fps8(const float* __restrict__ pts, float* __restrict__ out) {
    fps_body<8, false>(pts, out);
}

static size_t smem_bytes(int cs) {
    int ppc = NPTS / cs;
    return (size_t)(3 * ppc + 64 + 2 * cs * 8) * sizeof(float);
}

extern "C" void kernel_launch(void* const* d_in, const int* in_sizes, int n_in,
                              void* d_out, int out_size)
{
    (void)in_sizes; (void)n_in; (void)out_size;
    const float* pts = (const float*)d_in[0];   // point_coord (8, 131072, 3)
    float* out = (float*)d_out;                 // (8, 4096, 3)

    const size_t s16 = smem_bytes(16);
    const size_t s8  = smem_bytes(8);

    cudaFuncSetAttribute(fps16, cudaFuncAttributeNonPortableClusterSizeAllowed, 1);
    cudaFuncSetAttribute(fps16, cudaFuncAttributeMaxDynamicSharedMemorySize, (int)s16);
    cudaFuncSetAttribute(fps8,  cudaFuncAttributeMaxDynamicSharedMemorySize, (int)s8);
    cudaGetLastError();

    // Probe: can the device run 16-CTA clusters of this shape?
    int nc = 0;
    cudaLaunchConfig_t cfg = {};
    cfg.gridDim  = dim3(BATCH * 16, 1, 1);
    cfg.blockDim = dim3(NT, 1, 1);
    cfg.dynamicSmemBytes = s16;
    cudaLaunchAttribute at[1];
    at[0].id = cudaLaunchAttributeClusterDimension;
    at[0].val.clusterDim.x = 16;
    at[0].val.clusterDim.y = 1;
    at[0].val.clusterDim.z = 1;
    cfg.attrs = at;
    cfg.numAttrs = 1;
    cudaError_t e = cudaOccupancyMaxActiveClusters(&nc, fps16, &cfg);

    if (e == cudaSuccess && nc > 0) {
        fps16<<<BATCH * 16, NT, s16>>>(pts, out);
    } else {
        cudaGetLastError();
        fps8<<<BATCH * 8, NT, s8>>>(pts, out);
    }
}